// round 5
// baseline (speedup 1.0000x reference)
#include <cuda_runtime.h>
#include <cstdint>
#include <cstddef>

#define B_    256
#define N_    256
#define L_    1024
#define D_    256
#define KQ_   64
#define OUT_  64

// ---------------- scratch (device globals: allocation-free rule) -------------
__device__ float g_q[B_ * KQ_];                         // scaled q projections
__device__ float g_k[(size_t)N_ * L_ * KQ_];            // 64 MB
__device__ float g_v[(size_t)N_ * L_ * OUT_];           // 64 MB

using ull = unsigned long long;

// packed fp32x2 helpers (sm_103a fma.rn.f32x2 — 2x fp32 FMA throughput)
__device__ __forceinline__ ull pk2(float x, float y) {
    ull r; asm("mov.b64 %0, {%1, %2};" : "=l"(r) : "f"(x), "f"(y)); return r;
}
__device__ __forceinline__ void fma2(ull& a, ull b, ull c) {
    asm("fma.rn.f32x2 %0, %1, %2, %0;" : "+l"(a) : "l"(b), "l"(c));
}
__device__ __forceinline__ float2 up2(ull v) {
    float2 r; asm("mov.b64 {%0, %1}, %2;" : "=f"(r.x), "=f"(r.y) : "l"(v)); return r;
}
__device__ __forceinline__ float hsum2(ull v) { float2 p = up2(v); return p.x + p.y; }

// ---------------- kernel 1: q = 0.125 * queries @ Wq -------------------------
__global__ void proj_q_kernel(const float* __restrict__ queries,
                              const float* __restrict__ Wq) {
    __shared__ float srow[D_];
    int b = blockIdx.x, j = threadIdx.x;
    for (int d = j; d < D_; d += 64) srow[d] = queries[b * D_ + d];
    __syncthreads();
    float acc = 0.f;
#pragma unroll 8
    for (int d = 0; d < D_; d++) acc = fmaf(srow[d], Wq[d * KQ_ + j], acc);
    g_q[b * KQ_ + j] = acc * 0.125f;   // fold 1/sqrt(KQ) into q
}

// ---------------- kernel 2: k = keys@Wk, v = values@Wv (rows-tiled GEMM) -----
#define PROJ_ROWS 128
#define INPAD     258   // 4-row stride = 1032 floats ≡ 8 mod 32 banks: conflict-free

__global__ __launch_bounds__(256, 1)
void proj_kernel(const float* __restrict__ keys, const float* __restrict__ values,
                 const float* __restrict__ Wk, const float* __restrict__ Wv) {
    extern __shared__ float sm[];
    float* sW  = sm;                 // 256*64 = 16384 floats
    float* sIn = sm + D_ * KQ_;      // 128*258 floats

    const float* in; const float* W; float* out;
    if (blockIdx.y == 0) { in = keys;   W = Wk; out = g_k; }
    else                 { in = values; W = Wv; out = g_v; }

    int tid = threadIdx.x;

    // load full weight matrix to SMEM (float4 coalesced)
    const float4* W4 = (const float4*)W;
    float4* sW4 = (float4*)sW;
    for (int m = tid; m < (D_ * KQ_) / 4; m += 256) sW4[m] = W4[m];

    // load 128-row input tile (float4 gmem, float2 SMEM stores to honor pad 258)
    size_t rowbase = (size_t)blockIdx.x * PROJ_ROWS;
    const float4* in4 = (const float4*)(in + rowbase * D_);
    for (int m = tid; m < PROJ_ROWS * D_ / 4; m += 256) {
        int row = m >> 6, f = m & 63;
        float4 v = in4[m];
        float* dst = sIn + row * INPAD + (f << 2);
        *(float2*)dst       = make_float2(v.x, v.y);
        *(float2*)(dst + 2) = make_float2(v.z, v.w);
    }
    __syncthreads();

    int tx = tid & 7, ty = tid >> 3;
    int r0 = ty << 2;                 // 4 rows per thread
    // 8 cols per thread (tx*8..tx*8+7) as 4 packed f32x2 accumulators per row
    ull acc[4][4];
#pragma unroll
    for (int i = 0; i < 4; i++)
#pragma unroll
        for (int c = 0; c < 4; c++) acc[i][c] = 0ull;

#pragma unroll 4
    for (int d = 0; d < D_; d++) {
        float a0 = sIn[(r0 + 0) * INPAD + d];
        float a1 = sIn[(r0 + 1) * INPAD + d];
        float a2 = sIn[(r0 + 2) * INPAD + d];
        float a3 = sIn[(r0 + 3) * INPAD + d];
        ull p0 = pk2(a0, a0), p1 = pk2(a1, a1), p2 = pk2(a2, a2), p3 = pk2(a3, a3);
        const float* wr = sW + d * KQ_ + (tx << 3);
        ulonglong2 b01 = *(const ulonglong2*)(wr);
        ulonglong2 b23 = *(const ulonglong2*)(wr + 4);
        fma2(acc[0][0], p0, b01.x); fma2(acc[0][1], p0, b01.y);
        fma2(acc[0][2], p0, b23.x); fma2(acc[0][3], p0, b23.y);
        fma2(acc[1][0], p1, b01.x); fma2(acc[1][1], p1, b01.y);
        fma2(acc[1][2], p1, b23.x); fma2(acc[1][3], p1, b23.y);
        fma2(acc[2][0], p2, b01.x); fma2(acc[2][1], p2, b01.y);
        fma2(acc[2][2], p2, b23.x); fma2(acc[2][3], p2, b23.y);
        fma2(acc[3][0], p3, b01.x); fma2(acc[3][1], p3, b01.y);
        fma2(acc[3][2], p3, b23.x); fma2(acc[3][3], p3, b23.y);
    }

#pragma unroll
    for (int i = 0; i < 4; i++) {
        float2 p0 = up2(acc[i][0]), p1 = up2(acc[i][1]);
        float2 p2 = up2(acc[i][2]), p3 = up2(acc[i][3]);
        float* op = out + (rowbase + r0 + i) * (size_t)KQ_ + (tx << 3);
        *(float4*)op       = make_float4(p0.x, p0.y, p1.x, p1.y);
        *(float4*)(op + 4) = make_float4(p2.x, p2.y, p3.x, p3.y);
    }
}

// ------------- kernel 3: fused logits + softmax + attn + attn@v --------------
// block = (n, 32 b-rows). s-tile [32][1024] stays in SMEM (fp32).
#define ROWS_C 32
#define SSTR   1032   // row stride ≡ 8 mod 32 banks
#define KPAD   68     // k/v chunk row stride: Δtx=1 row → 68 ≡ 4 banks, 16B-aligned

__global__ __launch_bounds__(256, 1)
void attn_kernel(float* __restrict__ resOut, float* __restrict__ attnOut) {
    extern __shared__ float sm[];
    float* sS  = sm;                   // 32*1032 floats
    float* sKV = sm + ROWS_C * SSTR;   // 256*68 floats (k chunk, reused for v)

    int n   = blockIdx.y;
    int b0  = blockIdx.x * ROWS_C;
    int tid = threadIdx.x;
    int tx  = tid & 7, ty = tid >> 3;  // warp = 4 rows x 8 lane-groups
    int b   = b0 + ty;

    // q row (scaled) packed into 32 f32x2 registers
    ull q2[32];
    const float2* qp = (const float2*)(g_q + b * KQ_);
#pragma unroll
    for (int j = 0; j < 32; j++) { float2 t = qp[j]; q2[j] = pk2(t.x, t.y); }

    float vmax = -3.402823466e38f;
    float* srow = sS + ty * SSTR;

    // ---- phase 1: s = q . k^T over L in 4 chunks of 256 ----
    for (int ch = 0; ch < 4; ch++) {
        int lbase = ch << 8;
        __syncthreads();
        const float4* g4 = (const float4*)(g_k + ((size_t)n * L_ + lbase) * KQ_);
        for (int m = tid; m < 4096; m += 256) {
            int row = m >> 4, f = m & 15;
            *(float4*)(sKV + row * KPAD + (f << 2)) = g4[m];
        }
        __syncthreads();
#pragma unroll 1
        for (int li = 0; li < 32; li++) {
            int lloc = tx + (li << 3);
            const float* kr = sKV + lloc * KPAD;
            ull a0 = 0, a1 = 0, a2 = 0, a3 = 0;   // 4 chains for ILP
#pragma unroll
            for (int j = 0; j < 32; j += 4) {
                ulonglong2 kA = *(const ulonglong2*)(kr + (j << 1));
                ulonglong2 kB = *(const ulonglong2*)(kr + (j << 1) + 4);
                fma2(a0, q2[j],     kA.x);
                fma2(a1, q2[j + 1], kA.y);
                fma2(a2, q2[j + 2], kB.x);
                fma2(a3, q2[j + 3], kB.y);
            }
            float s = (hsum2(a0) + hsum2(a1)) + (hsum2(a2) + hsum2(a3));
            vmax = fmaxf(vmax, s);
            srow[lbase + lloc] = s;
        }
    }

    // ---- phase 2: softmax (each thread touches only its own row slots) ----
    float m = vmax;
    m = fmaxf(m, __shfl_xor_sync(0xffffffffu, m, 1));
    m = fmaxf(m, __shfl_xor_sync(0xffffffffu, m, 2));
    m = fmaxf(m, __shfl_xor_sync(0xffffffffu, m, 4));
    float ssum = 0.f;
#pragma unroll 4
    for (int li = 0; li < 128; li++) {
        int l = tx + (li << 3);
        float e = __expf(srow[l] - m);
        srow[l] = e;
        ssum += e;
    }
    ssum += __shfl_xor_sync(0xffffffffu, ssum, 1);
    ssum += __shfl_xor_sync(0xffffffffu, ssum, 2);
    ssum += __shfl_xor_sync(0xffffffffu, ssum, 4);
    float inv = 1.0f / ssum;

    size_t aoff = ((size_t)n * B_ + b) * L_;
#pragma unroll 4
    for (int li = 0; li < 128; li++) {
        int l = tx + (li << 3);
        attnOut[aoff + l] = srow[l] * inv;   // normalized attention out
    }

    // ---- phase 3: result[b][n][:] = (e @ v[n]) * inv ----
    ull o0 = 0, o1 = 0, o2 = 0, o3 = 0;      // 8 out cols as 4 f32x2
    for (int ch = 0; ch < 4; ch++) {
        int lbase = ch << 8;
        __syncthreads();                      // everyone past phase 1/2 before sKV reuse
        const float4* g4 = (const float4*)(g_v + ((size_t)n * L_ + lbase) * OUT_);
        for (int mm = tid; mm < 4096; mm += 256) {
            int row = mm >> 4, f = mm & 15;
            *(float4*)(sKV + row * KPAD + (f << 2)) = g4[mm];
        }
        __syncthreads();
        const float* ebase = srow + lbase;
#pragma unroll 4
        for (int lloc = 0; lloc < 256; lloc++) {
            float e = ebase[lloc];
            ull e2 = pk2(e, e);
            const float* vr = sKV + lloc * KPAD + (tx << 3);
            ulonglong2 vA = *(const ulonglong2*)(vr);
            ulonglong2 vB = *(const ulonglong2*)(vr + 4);
            fma2(o0, e2, vA.x); fma2(o1, e2, vA.y);
            fma2(o2, e2, vB.x); fma2(o3, e2, vB.y);
        }
    }

    float2 p0 = up2(o0), p1 = up2(o1), p2 = up2(o2), p3 = up2(o3);
    float* op = resOut + ((size_t)b * N_ + n) * OUT_ + (tx << 3);
    *(float4*)op       = make_float4(p0.x * inv, p0.y * inv, p1.x * inv, p1.y * inv);
    *(float4*)(op + 4) = make_float4(p2.x * inv, p2.y * inv, p3.x * inv, p3.y * inv);
}

// ----------------------------- launcher --------------------------------------
extern "C" void kernel_launch(void* const* d_in, const int* in_sizes, int n_in,
                              void* d_out, int out_size) {
    const float* queries = (const float*)d_in[0];
    const float* keys    = (const float*)d_in[1];
    const float* values  = (const float*)d_in[2];
    const float* Wq      = (const float*)d_in[3];
    const float* Wk      = (const float*)d_in[4];
    const float* Wv      = (const float*)d_in[5];

    float* resOut  = (float*)d_out;                         // [B, N, OUT]
    float* attnOut = resOut + (size_t)B_ * N_ * OUT_;       // [N, B, L]

    const int SMEM_PROJ = (int)((D_ * KQ_ + PROJ_ROWS * INPAD) * sizeof(float));  // ~193 KB
    const int SMEM_ATTN = (int)((ROWS_C * SSTR + 256 * KPAD) * sizeof(float));    // ~197 KB
    cudaFuncSetAttribute(proj_kernel, cudaFuncAttributeMaxDynamicSharedMemorySize, SMEM_PROJ);
    cudaFuncSetAttribute(attn_kernel, cudaFuncAttributeMaxDynamicSharedMemorySize, SMEM_ATTN);

    proj_q_kernel<<<B_, 64>>>(queries, Wq);
    proj_kernel<<<dim3((N_ * L_) / PROJ_ROWS, 2), 256, SMEM_PROJ>>>(keys, values, Wk, Wv);
    attn_kernel<<<dim3(B_ / ROWS_C, N_), 256, SMEM_ATTN>>>(resOut, attnOut);
}

// round 6
// speedup vs baseline: 1.0006x; 1.0006x over previous
#include <cuda_runtime.h>
#include <cstdint>
#include <cstddef>

#define B_    256
#define N_    256
#define L_    1024
#define D_    256
#define KQ_   64
#define OUT_  64

// ---------------- scratch (device globals: allocation-free rule) -------------
__device__ float g_q[B_ * KQ_];                         // scaled q projections
__device__ float g_k[(size_t)N_ * L_ * KQ_];            // 64 MB
__device__ float g_v[(size_t)N_ * L_ * OUT_];           // 64 MB

using ull = unsigned long long;

// packed fp32x2 helpers (sm_103a fma.rn.f32x2 — 2x fp32 FMA throughput)
__device__ __forceinline__ ull pk2(float x, float y) {
    ull r; asm("mov.b64 %0, {%1, %2};" : "=l"(r) : "f"(x), "f"(y)); return r;
}
__device__ __forceinline__ void fma2(ull& a, ull b, ull c) {
    asm("fma.rn.f32x2 %0, %1, %2, %0;" : "+l"(a) : "l"(b), "l"(c));
}
__device__ __forceinline__ float2 up2(ull v) {
    float2 r; asm("mov.b64 {%0, %1}, %2;" : "=f"(r.x), "=f"(r.y) : "l"(v)); return r;
}
__device__ __forceinline__ float hsum2(ull v) { float2 p = up2(v); return p.x + p.y; }

// ---------------- kernel 1: q = 0.125 * queries @ Wq -------------------------
__global__ void proj_q_kernel(const float* __restrict__ queries,
                              const float* __restrict__ Wq) {
    __shared__ float srow[D_];
    int b = blockIdx.x, j = threadIdx.x;
    for (int d = j; d < D_; d += 64) srow[d] = queries[b * D_ + d];
    __syncthreads();
    float acc = 0.f;
#pragma unroll 8
    for (int d = 0; d < D_; d++) acc = fmaf(srow[d], Wq[d * KQ_ + j], acc);
    g_q[b * KQ_ + j] = acc * 0.125f;   // fold 1/sqrt(KQ) into q
}

// ---------------- kernel 2: k = keys@Wk, v = values@Wv (rows-tiled GEMM) -----
#define PROJ_ROWS 128
#define INPAD     258   // 4-row stride = 1032 floats ≡ 8 mod 32 banks: conflict-free

__global__ __launch_bounds__(256, 1)
void proj_kernel(const float* __restrict__ keys, const float* __restrict__ values,
                 const float* __restrict__ Wk, const float* __restrict__ Wv) {
    extern __shared__ float sm[];
    float* sW  = sm;                 // 256*64 = 16384 floats
    float* sIn = sm + D_ * KQ_;      // 128*258 floats

    const float* in; const float* W; float* out;
    if (blockIdx.y == 0) { in = keys;   W = Wk; out = g_k; }
    else                 { in = values; W = Wv; out = g_v; }

    int tid = threadIdx.x;

    // load full weight matrix to SMEM (float4 coalesced)
    const float4* W4 = (const float4*)W;
    float4* sW4 = (float4*)sW;
    for (int m = tid; m < (D_ * KQ_) / 4; m += 256) sW4[m] = W4[m];

    // load 128-row input tile (float4 gmem, float2 SMEM stores to honor pad 258)
    size_t rowbase = (size_t)blockIdx.x * PROJ_ROWS;
    const float4* in4 = (const float4*)(in + rowbase * D_);
    for (int m = tid; m < PROJ_ROWS * D_ / 4; m += 256) {
        int row = m >> 6, f = m & 63;
        float4 v = in4[m];
        float* dst = sIn + row * INPAD + (f << 2);
        *(float2*)dst       = make_float2(v.x, v.y);
        *(float2*)(dst + 2) = make_float2(v.z, v.w);
    }
    __syncthreads();

    int tx = tid & 7, ty = tid >> 3;
    int r0 = ty << 2;                 // 4 rows per thread
    // 8 cols per thread (tx*8..tx*8+7) as 4 packed f32x2 accumulators per row
    ull acc[4][4];
#pragma unroll
    for (int i = 0; i < 4; i++)
#pragma unroll
        for (int c = 0; c < 4; c++) acc[i][c] = 0ull;

#pragma unroll 4
    for (int d = 0; d < D_; d++) {
        float a0 = sIn[(r0 + 0) * INPAD + d];
        float a1 = sIn[(r0 + 1) * INPAD + d];
        float a2 = sIn[(r0 + 2) * INPAD + d];
        float a3 = sIn[(r0 + 3) * INPAD + d];
        ull p0 = pk2(a0, a0), p1 = pk2(a1, a1), p2 = pk2(a2, a2), p3 = pk2(a3, a3);
        const float* wr = sW + d * KQ_ + (tx << 3);
        ulonglong2 b01 = *(const ulonglong2*)(wr);
        ulonglong2 b23 = *(const ulonglong2*)(wr + 4);
        fma2(acc[0][0], p0, b01.x); fma2(acc[0][1], p0, b01.y);
        fma2(acc[0][2], p0, b23.x); fma2(acc[0][3], p0, b23.y);
        fma2(acc[1][0], p1, b01.x); fma2(acc[1][1], p1, b01.y);
        fma2(acc[1][2], p1, b23.x); fma2(acc[1][3], p1, b23.y);
        fma2(acc[2][0], p2, b01.x); fma2(acc[2][1], p2, b01.y);
        fma2(acc[2][2], p2, b23.x); fma2(acc[2][3], p2, b23.y);
        fma2(acc[3][0], p3, b01.x); fma2(acc[3][1], p3, b01.y);
        fma2(acc[3][2], p3, b23.x); fma2(acc[3][3], p3, b23.y);
    }

#pragma unroll
    for (int i = 0; i < 4; i++) {
        float2 p0 = up2(acc[i][0]), p1 = up2(acc[i][1]);
        float2 p2 = up2(acc[i][2]), p3 = up2(acc[i][3]);
        float* op = out + (rowbase + r0 + i) * (size_t)KQ_ + (tx << 3);
        *(float4*)op       = make_float4(p0.x, p0.y, p1.x, p1.y);
        *(float4*)(op + 4) = make_float4(p2.x, p2.y, p3.x, p3.y);
    }
}

// ------------- kernel 3: fused logits + softmax + attn + attn@v --------------
// block = (n, 32 b-rows). s-tile [32][1024] stays in SMEM (fp32).
#define ROWS_C 32
#define SSTR   1032   // row stride ≡ 8 mod 32 banks
#define KPAD   68     // k/v chunk row stride: Δtx=1 row → 68 ≡ 4 banks, 16B-aligned

__global__ __launch_bounds__(256, 1)
void attn_kernel(float* __restrict__ resOut, float* __restrict__ attnOut) {
    extern __shared__ float sm[];
    float* sS  = sm;                   // 32*1032 floats
    float* sKV = sm + ROWS_C * SSTR;   // 256*68 floats (k chunk, reused for v)

    int n   = blockIdx.y;
    int b0  = blockIdx.x * ROWS_C;
    int tid = threadIdx.x;
    int tx  = tid & 7, ty = tid >> 3;  // warp = 4 rows x 8 lane-groups
    int b   = b0 + ty;

    // q row (scaled) packed into 32 f32x2 registers
    ull q2[32];
    const float2* qp = (const float2*)(g_q + b * KQ_);
#pragma unroll
    for (int j = 0; j < 32; j++) { float2 t = qp[j]; q2[j] = pk2(t.x, t.y); }

    float vmax = -3.402823466e38f;
    float* srow = sS + ty * SSTR;

    // ---- phase 1: s = q . k^T over L in 4 chunks of 256 ----
    for (int ch = 0; ch < 4; ch++) {
        int lbase = ch << 8;
        __syncthreads();
        const float4* g4 = (const float4*)(g_k + ((size_t)n * L_ + lbase) * KQ_);
        for (int m = tid; m < 4096; m += 256) {
            int row = m >> 4, f = m & 15;
            *(float4*)(sKV + row * KPAD + (f << 2)) = g4[m];
        }
        __syncthreads();
#pragma unroll 1
        for (int li = 0; li < 32; li++) {
            int lloc = tx + (li << 3);
            const float* kr = sKV + lloc * KPAD;
            ull a0 = 0, a1 = 0, a2 = 0, a3 = 0;   // 4 chains for ILP
#pragma unroll
            for (int j = 0; j < 32; j += 4) {
                ulonglong2 kA = *(const ulonglong2*)(kr + (j << 1));
                ulonglong2 kB = *(const ulonglong2*)(kr + (j << 1) + 4);
                fma2(a0, q2[j],     kA.x);
                fma2(a1, q2[j + 1], kA.y);
                fma2(a2, q2[j + 2], kB.x);
                fma2(a3, q2[j + 3], kB.y);
            }
            float s = (hsum2(a0) + hsum2(a1)) + (hsum2(a2) + hsum2(a3));
            vmax = fmaxf(vmax, s);
            srow[lbase + lloc] = s;
        }
    }

    // ---- phase 2: softmax (each thread touches only its own row slots) ----
    float m = vmax;
    m = fmaxf(m, __shfl_xor_sync(0xffffffffu, m, 1));
    m = fmaxf(m, __shfl_xor_sync(0xffffffffu, m, 2));
    m = fmaxf(m, __shfl_xor_sync(0xffffffffu, m, 4));
    float ssum = 0.f;
#pragma unroll 4
    for (int li = 0; li < 128; li++) {
        int l = tx + (li << 3);
        float e = __expf(srow[l] - m);
        srow[l] = e;
        ssum += e;
    }
    ssum += __shfl_xor_sync(0xffffffffu, ssum, 1);
    ssum += __shfl_xor_sync(0xffffffffu, ssum, 2);
    ssum += __shfl_xor_sync(0xffffffffu, ssum, 4);
    float inv = 1.0f / ssum;

    size_t aoff = ((size_t)n * B_ + b) * L_;
#pragma unroll 4
    for (int li = 0; li < 128; li++) {
        int l = tx + (li << 3);
        attnOut[aoff + l] = srow[l] * inv;   // normalized attention out
    }

    // ---- phase 3: result[b][n][:] = (e @ v[n]) * inv ----
    ull o0 = 0, o1 = 0, o2 = 0, o3 = 0;      // 8 out cols as 4 f32x2
    for (int ch = 0; ch < 4; ch++) {
        int lbase = ch << 8;
        __syncthreads();                      // everyone past phase 1/2 before sKV reuse
        const float4* g4 = (const float4*)(g_v + ((size_t)n * L_ + lbase) * OUT_);
        for (int mm = tid; mm < 4096; mm += 256) {
            int row = mm >> 4, f = mm & 15;
            *(float4*)(sKV + row * KPAD + (f << 2)) = g4[mm];
        }
        __syncthreads();
        const float* ebase = srow + lbase;
#pragma unroll 4
        for (int lloc = 0; lloc < 256; lloc++) {
            float e = ebase[lloc];
            ull e2 = pk2(e, e);
            const float* vr = sKV + lloc * KPAD + (tx << 3);
            ulonglong2 vA = *(const ulonglong2*)(vr);
            ulonglong2 vB = *(const ulonglong2*)(vr + 4);
            fma2(o0, e2, vA.x); fma2(o1, e2, vA.y);
            fma2(o2, e2, vB.x); fma2(o3, e2, vB.y);
        }
    }

    float2 p0 = up2(o0), p1 = up2(o1), p2 = up2(o2), p3 = up2(o3);
    float* op = resOut + ((size_t)b * N_ + n) * OUT_ + (tx << 3);
    *(float4*)op       = make_float4(p0.x * inv, p0.y * inv, p1.x * inv, p1.y * inv);
    *(float4*)(op + 4) = make_float4(p2.x * inv, p2.y * inv, p3.x * inv, p3.y * inv);
}

// ----------------------------- launcher --------------------------------------
extern "C" void kernel_launch(void* const* d_in, const int* in_sizes, int n_in,
                              void* d_out, int out_size) {
    const float* queries = (const float*)d_in[0];
    const float* keys    = (const float*)d_in[1];
    const float* values  = (const float*)d_in[2];
    const float* Wq      = (const float*)d_in[3];
    const float* Wk      = (const float*)d_in[4];
    const float* Wv      = (const float*)d_in[5];

    float* resOut  = (float*)d_out;                         // [B, N, OUT]
    float* attnOut = resOut + (size_t)B_ * N_ * OUT_;       // [N, B, L]

    const int SMEM_PROJ = (int)((D_ * KQ_ + PROJ_ROWS * INPAD) * sizeof(float));  // ~193 KB
    const int SMEM_ATTN = (int)((ROWS_C * SSTR + 256 * KPAD) * sizeof(float));    // ~197 KB
    cudaFuncSetAttribute(proj_kernel, cudaFuncAttributeMaxDynamicSharedMemorySize, SMEM_PROJ);
    cudaFuncSetAttribute(attn_kernel, cudaFuncAttributeMaxDynamicSharedMemorySize, SMEM_ATTN);

    proj_q_kernel<<<B_, 64>>>(queries, Wq);
    proj_kernel<<<dim3((N_ * L_) / PROJ_ROWS, 2), 256, SMEM_PROJ>>>(keys, values, Wk, Wv);
    attn_kernel<<<dim3(B_ / ROWS_C, N_), 256, SMEM_ATTN>>>(resOut, attnOut);
}

// round 9
// speedup vs baseline: 1.8189x; 1.8178x over previous
#include <cuda_runtime.h>
#include <cstdint>
#include <cstddef>

#define B_    256
#define N_    256
#define L_    1024
#define D_    256
#define KQ_   64
#define OUT_  64

// ---------------- scratch (device globals: allocation-free rule) -------------
__device__ float g_q[B_ * KQ_];                         // scaled q projections
__device__ float g_k[(size_t)N_ * L_ * KQ_];            // 64 MB
__device__ float g_v[(size_t)N_ * L_ * OUT_];           // 64 MB

// ---------------- tf32 split helpers -----------------------------------------
__device__ __forceinline__ uint32_t f2tf(float f) {
    uint32_t r; asm("cvt.rna.tf32.f32 %0, %1;" : "=r"(r) : "f"(f)); return r;
}
// x ~= hi + lo with hi,lo tf32 (each valid fp32 bit patterns, low mantissa zeroed)
__device__ __forceinline__ void tfsplit(float f, uint32_t& hi, uint32_t& lo) {
    hi = f2tf(f);
    lo = f2tf(f - __uint_as_float(hi));
}

__device__ __forceinline__ void mma8(float* c,
                                     uint32_t a0, uint32_t a1, uint32_t a2, uint32_t a3,
                                     uint32_t b0, uint32_t b1) {
    asm volatile(
        "mma.sync.aligned.m16n8k8.row.col.f32.tf32.tf32.f32 "
        "{%0,%1,%2,%3}, {%4,%5,%6,%7}, {%8,%9}, {%0,%1,%2,%3};"
        : "+f"(c[0]), "+f"(c[1]), "+f"(c[2]), "+f"(c[3])
        : "r"(a0), "r"(a1), "r"(a2), "r"(a3), "r"(b0), "r"(b1));
}

// split-tf32 product: (ah+al) x (bh+bl) ~= ah*bh + al*bh + ah*bl  (al*bl ~2^-22, dropped)
__device__ __forceinline__ void mma_split(float* c, const uint32_t* ah, const uint32_t* al,
                                          uint32_t bh0, uint32_t bh1,
                                          uint32_t bl0, uint32_t bl1) {
    mma8(c, ah[0], ah[1], ah[2], ah[3], bh0, bh1);
    mma8(c, al[0], al[1], al[2], al[3], bh0, bh1);
    mma8(c, ah[0], ah[1], ah[2], ah[3], bl0, bl1);
}

// ---------------- kernel 1: q = 0.125 * queries @ Wq (fp32, tiny) ------------
__global__ void proj_q_kernel(const float* __restrict__ queries,
                              const float* __restrict__ Wq) {
    __shared__ float srow[D_];
    int b = blockIdx.x, j = threadIdx.x;
    for (int d = j; d < D_; d += 64) srow[d] = queries[b * D_ + d];
    __syncthreads();
    float acc = 0.f;
#pragma unroll 8
    for (int d = 0; d < D_; d++) acc = fmaf(srow[d], Wq[d * KQ_ + j], acc);
    g_q[b * KQ_ + j] = acc * 0.125f;   // fold 1/sqrt(KQ) into q
}

// ---------------- kernel 2: k = keys@Wk, v = values@Wv (tensor core) ---------
// GEMM [rows x 256] @ [256 x 64]. CTA tile: 128 rows. 8 warps = 4(m) x 2(n),
// warp tile 32x32. split-tf32, fp32 accumulate.
#define PR_ROWS 128
#define ASTR    260   // row stride mod 32 banks == 4: A-frag pattern conflict-free
#define WSTR    72    // row stride mod 32 banks == 8: B-frag pattern conflict-free

__global__ __launch_bounds__(256, 1)
void proj_kernel(const float* __restrict__ keys, const float* __restrict__ values,
                 const float* __restrict__ Wk, const float* __restrict__ Wv) {
    extern __shared__ float sm[];
    float* sW = sm;                    // [256][72]
    float* sA = sm + 256 * WSTR;       // [128][260]

    const float* in; const float* W; float* out;
    if (blockIdx.y == 0) { in = keys;   W = Wk; out = g_k; }
    else                 { in = values; W = Wv; out = g_v; }

    int tid = threadIdx.x;

    // load W [256 x 64] -> sW (float4 coalesced, stride 72 is 16B-aligned)
    const float4* W4 = (const float4*)W;
    for (int m = tid; m < 4096; m += 256) {
        int d = m >> 4, c4 = m & 15;
        *(float4*)(sW + d * WSTR + (c4 << 2)) = W4[m];
    }
    // load A tile [128 x 256] -> sA
    size_t rowbase = (size_t)blockIdx.x * PR_ROWS;
    const float4* in4 = (const float4*)(in + rowbase * D_);
    for (int m = tid; m < 8192; m += 256) {
        int r = m >> 6, c4 = m & 63;
        *(float4*)(sA + r * ASTR + (c4 << 2)) = in4[m];
    }
    __syncthreads();

    int w = tid >> 5, lane = tid & 31;
    int gi = lane >> 2, ti = lane & 3;
    int m0 = (w >> 1) << 5;            // 0,32,64,96
    int n0 = (w & 1) << 5;             // 0,32

    float c[2][4][4];
#pragma unroll
    for (int mf = 0; mf < 2; mf++)
#pragma unroll
        for (int nf = 0; nf < 4; nf++)
#pragma unroll
            for (int i = 0; i < 4; i++) c[mf][nf][i] = 0.f;

    for (int k0 = 0; k0 < D_; k0 += 8) {
        uint32_t ah[2][4], al[2][4];
#pragma unroll
        for (int mf = 0; mf < 2; mf++) {
            const float* ap = sA + (m0 + mf * 16 + gi) * ASTR + k0 + ti;
            tfsplit(ap[0],            ah[mf][0], al[mf][0]);
            tfsplit(ap[8 * ASTR],     ah[mf][1], al[mf][1]);
            tfsplit(ap[4],            ah[mf][2], al[mf][2]);
            tfsplit(ap[8 * ASTR + 4], ah[mf][3], al[mf][3]);
        }
#pragma unroll
        for (int nf = 0; nf < 4; nf++) {
            const float* bp = sW + (k0 + ti) * WSTR + n0 + nf * 8 + gi;
            uint32_t bh0, bl0, bh1, bl1;
            tfsplit(bp[0],        bh0, bl0);
            tfsplit(bp[4 * WSTR], bh1, bl1);
#pragma unroll
            for (int mf = 0; mf < 2; mf++)
                mma_split(c[mf][nf], ah[mf], al[mf], bh0, bh1, bl0, bl1);
        }
    }

#pragma unroll
    for (int mf = 0; mf < 2; mf++)
#pragma unroll
        for (int nf = 0; nf < 4; nf++) {
            size_t row = rowbase + m0 + mf * 16 + gi;
            int col = n0 + nf * 8 + (ti << 1);
            *(float2*)(out + row * KQ_ + col)       = make_float2(c[mf][nf][0], c[mf][nf][1]);
            *(float2*)(out + (row + 8) * KQ_ + col) = make_float2(c[mf][nf][2], c[mf][nf][3]);
        }
}

// ------------- kernel 3: fused logits + softmax + attn + attn@v --------------
// block = (n, 32 b-rows). S [32x1024] fp32 in SMEM. Tensor-core logits and AV.
#define ROWS_C 32
#define SSTR   1028   // mod 32 == 4: phase-3 A-frag reads conflict-free
#define KSTR   68     // phase-1 K chunk stride (mod 32 == 4)
#define VSTR   72     // phase-3 V chunk stride (mod 32 == 8)
#define LCH    128    // L chunk rows

__global__ __launch_bounds__(256, 1)
void attn_kernel(float* __restrict__ resOut, float* __restrict__ attnOut) {
    extern __shared__ float sm[];
    float* sS   = sm;                          // 32*1028
    float* sKV  = sS + ROWS_C * SSTR;          // 128*72 (K chunks use stride 68)
    float* sQ   = sKV + LCH * VSTR;            // 32*68
    float* sInv = sQ + ROWS_C * 68;            // 32

    int n   = blockIdx.y;
    int b0  = blockIdx.x * ROWS_C;
    int tid = threadIdx.x;
    int w = tid >> 5, lane = tid & 31;
    int gi = lane >> 2, ti = lane & 3;

    // load Q rows [32 x 64] (already scaled by 0.125)
    {
        const float4* q4 = (const float4*)(g_q + b0 * KQ_);
        for (int m = tid; m < 512; m += 256) {
            int r = m >> 4, c4 = m & 15;
            *(float4*)(sQ + r * 68 + (c4 << 2)) = q4[m];
        }
    }

    // ---- phase 1: S = Q @ K^T, L in 8 chunks of 128; warp w owns l-width 16 --
    for (int ch = 0; ch < 8; ch++) {
        int lb = ch << 7;
        __syncthreads();
        const float4* g4 = (const float4*)(g_k + ((size_t)n * L_ + lb) * KQ_);
        for (int m = tid; m < 2048; m += 256) {
            int r = m >> 4, c4 = m & 15;
            *(float4*)(sKV + r * KSTR + (c4 << 2)) = g4[m];
        }
        __syncthreads();

        float c[2][2][4];
#pragma unroll
        for (int mf = 0; mf < 2; mf++)
#pragma unroll
            for (int nf = 0; nf < 2; nf++)
#pragma unroll
                for (int i = 0; i < 4; i++) c[mf][nf][i] = 0.f;

#pragma unroll
        for (int ks = 0; ks < 8; ks++) {
            int k0 = ks << 3;
            uint32_t ah[2][4], al[2][4];
#pragma unroll
            for (int mf = 0; mf < 2; mf++) {
                const float* ap = sQ + (mf * 16 + gi) * 68 + k0 + ti;
                tfsplit(ap[0],          ah[mf][0], al[mf][0]);
                tfsplit(ap[8 * 68],     ah[mf][1], al[mf][1]);
                tfsplit(ap[4],          ah[mf][2], al[mf][2]);
                tfsplit(ap[8 * 68 + 4], ah[mf][3], al[mf][3]);
            }
#pragma unroll
            for (int nf = 0; nf < 2; nf++) {
                // B = K^T: b0 = k[lcol][k0+ti], b1 = k[lcol][k0+ti+4]
                const float* bp = sKV + (w * 16 + nf * 8 + gi) * KSTR + k0 + ti;
                uint32_t bh0, bl0, bh1, bl1;
                tfsplit(bp[0], bh0, bl0);
                tfsplit(bp[4], bh1, bl1);
#pragma unroll
                for (int mf = 0; mf < 2; mf++)
                    mma_split(c[mf][nf], ah[mf], al[mf], bh0, bh1, bl0, bl1);
            }
        }
        // write S frags to sS
#pragma unroll
        for (int mf = 0; mf < 2; mf++)
#pragma unroll
            for (int nf = 0; nf < 2; nf++) {
                int row = mf * 16 + gi;
                int col = lb + w * 16 + nf * 8 + (ti << 1);
                *(float2*)(sS + row * SSTR + col)       = make_float2(c[mf][nf][0], c[mf][nf][1]);
                *(float2*)(sS + (row + 8) * SSTR + col) = make_float2(c[mf][nf][2], c[mf][nf][3]);
            }
    }
    __syncthreads();

    // ---- phase 2: softmax rows; keep unnormalized e in sS, write attn out ----
    {
        int ty = tid >> 3, tx = tid & 7;
        float* srow = sS + ty * SSTR;
        float vmax = -3.402823466e38f;
#pragma unroll 4
        for (int j = tx; j < L_; j += 8) vmax = fmaxf(vmax, srow[j]);
        vmax = fmaxf(vmax, __shfl_xor_sync(0xffffffffu, vmax, 1));
        vmax = fmaxf(vmax, __shfl_xor_sync(0xffffffffu, vmax, 2));
        vmax = fmaxf(vmax, __shfl_xor_sync(0xffffffffu, vmax, 4));
        float ssum = 0.f;
#pragma unroll 4
        for (int j = tx; j < L_; j += 8) {
            float e = __expf(srow[j] - vmax);
            srow[j] = e;
            ssum += e;
        }
        ssum += __shfl_xor_sync(0xffffffffu, ssum, 1);
        ssum += __shfl_xor_sync(0xffffffffu, ssum, 2);
        ssum += __shfl_xor_sync(0xffffffffu, ssum, 4);
        float inv = 1.0f / ssum;
        size_t aoff = ((size_t)n * B_ + (b0 + ty)) * L_;
#pragma unroll 4
        for (int j = tx; j < L_; j += 8) attnOut[aoff + j] = srow[j] * inv;
        if (tx == 0) sInv[ty] = inv;
    }

    // ---- phase 3: out[32x64] = P @ V; warp w owns out cols [8w, 8w+8) --------
    float acc[2][4];
#pragma unroll
    for (int mf = 0; mf < 2; mf++)
#pragma unroll
        for (int i = 0; i < 4; i++) acc[mf][i] = 0.f;

    for (int ch = 0; ch < 8; ch++) {
        int lb = ch << 7;
        __syncthreads();
        const float4* g4 = (const float4*)(g_v + ((size_t)n * L_ + lb) * OUT_);
        for (int m = tid; m < 2048; m += 256) {
            int r = m >> 4, c4 = m & 15;
            *(float4*)(sKV + r * VSTR + (c4 << 2)) = g4[m];
        }
        __syncthreads();

#pragma unroll 2
        for (int ks = 0; ks < 16; ks++) {
            int l0 = ks << 3;
            uint32_t ah[2][4], al[2][4];
#pragma unroll
            for (int mf = 0; mf < 2; mf++) {
                const float* ap = sS + (mf * 16 + gi) * SSTR + lb + l0 + ti;
                tfsplit(ap[0],            ah[mf][0], al[mf][0]);
                tfsplit(ap[8 * SSTR],     ah[mf][1], al[mf][1]);
                tfsplit(ap[4],            ah[mf][2], al[mf][2]);
                tfsplit(ap[8 * SSTR + 4], ah[mf][3], al[mf][3]);
            }
            // B = V chunk: b0 = v[l0+ti][8w+gi], b1 = v[l0+ti+4][8w+gi]
            const float* bp = sKV + (l0 + ti) * VSTR + w * 8 + gi;
            uint32_t bh0, bl0, bh1, bl1;
            tfsplit(bp[0],        bh0, bl0);
            tfsplit(bp[4 * VSTR], bh1, bl1);
#pragma unroll
            for (int mf = 0; mf < 2; mf++)
                mma_split(acc[mf], ah[mf], al[mf], bh0, bh1, bl0, bl1);
        }
    }

    // epilogue: scale by 1/rowsum, store result [B][N][64]
#pragma unroll
    for (int mf = 0; mf < 2; mf++) {
        int row = mf * 16 + gi;
        int col = w * 8 + (ti << 1);
        float i0 = sInv[row], i1 = sInv[row + 8];
        float* op0 = resOut + ((size_t)(b0 + row) * N_ + n) * OUT_ + col;
        float* op1 = resOut + ((size_t)(b0 + row + 8) * N_ + n) * OUT_ + col;
        *(float2*)op0 = make_float2(acc[mf][0] * i0, acc[mf][1] * i0);
        *(float2*)op1 = make_float2(acc[mf][2] * i1, acc[mf][3] * i1);
    }
}

// ----------------------------- launcher --------------------------------------
extern "C" void kernel_launch(void* const* d_in, const int* in_sizes, int n_in,
                              void* d_out, int out_size) {
    const float* queries = (const float*)d_in[0];
    const float* keys    = (const float*)d_in[1];
    const float* values  = (const float*)d_in[2];
    const float* Wq      = (const float*)d_in[3];
    const float* Wk      = (const float*)d_in[4];
    const float* Wv      = (const float*)d_in[5];

    float* resOut  = (float*)d_out;                         // [B, N, OUT]
    float* attnOut = resOut + (size_t)B_ * N_ * OUT_;       // [N, B, L]

    const int SMEM_PROJ = (int)((256 * WSTR + PR_ROWS * ASTR) * sizeof(float));            // ~202 KB
    const int SMEM_ATTN = (int)((ROWS_C * SSTR + LCH * VSTR + ROWS_C * 68 + 32) * sizeof(float)); // ~173 KB
    cudaFuncSetAttribute(proj_kernel, cudaFuncAttributeMaxDynamicSharedMemorySize, SMEM_PROJ);
    cudaFuncSetAttribute(attn_kernel, cudaFuncAttributeMaxDynamicSharedMemorySize, SMEM_ATTN);

    proj_q_kernel<<<B_, 64>>>(queries, Wq);
    proj_kernel<<<dim3((N_ * L_) / PR_ROWS, 2), 256, SMEM_PROJ>>>(keys, values, Wk, Wv);
    attn_kernel<<<dim3(B_ / ROWS_C, N_), 256, SMEM_ATTN>>>(resOut, attnOut);
}

// round 12
// speedup vs baseline: 2.8604x; 1.5726x over previous
#include <cuda_runtime.h>
#include <cstdint>
#include <cstddef>

#define B_    256
#define N_    256
#define L_    1024
#define D_    256
#define KQ_   64
#define OUT_  64

// 0.125 (=1/sqrt(KQ)) * log2(e): softmax computed in exp2 domain
#define QSCALE 0.18033688011112042f

// ---------------- scratch (device globals: allocation-free rule) -------------
// packed format: u32 = (bf16(hi) << 16) | bf16(lo),  value ~= hi + lo
__device__ uint32_t g_q_pk[B_ * KQ_];                       // scaled q
__device__ uint32_t g_k_pk[(size_t)N_ * L_ * KQ_];          // 64 MB
__device__ uint32_t g_v_pk[(size_t)N_ * L_ * OUT_];         // 64 MB
__device__ uint32_t g_wt_pk[2][KQ_][D_];                    // Wk^T, Wv^T packed

// ---------------- bf16-split helpers ------------------------------------------
__device__ __forceinline__ uint32_t prmt_(uint32_t a, uint32_t b, uint32_t sel) {
    uint32_t d; asm("prmt.b32 %0, %1, %2, %3;" : "=r"(d) : "r"(a), "r"(b), "r"(sel));
    return d;
}
__device__ __forceinline__ uint32_t cvt_bf16x2_(float hi_arg, float lo_arg) {
    // d<31:16> = bf16(hi_arg), d<15:0> = bf16(lo_arg)
    uint32_t d; asm("cvt.rn.bf16x2.f32 %0, %1, %2;" : "=r"(d) : "f"(hi_arg), "f"(lo_arg));
    return d;
}
// pack fp32 f -> (trunc-bf16 hi in high16, rn-bf16 of residual in low16)
__device__ __forceinline__ uint32_t pack_split(float f) {
    float hif = __uint_as_float(__float_as_uint(f) & 0xffff0000u);
    float lo  = f - hif;
    uint32_t t = cvt_bf16x2_(lo, lo);
    return prmt_(t, __float_as_uint(f), 0x7610);   // {t.b0,t.b1,f.b2,f.b3}
}
// two packed words (elem j, j+1) -> mma bf16x2 regs (hi-pair, lo-pair)
__device__ __forceinline__ void unpack_pair(uint2 w, uint32_t& hi, uint32_t& lo) {
    hi = prmt_(w.x, w.y, 0x7632);
    lo = prmt_(w.x, w.y, 0x5410);
}
// two fp32 -> split pair regs (hi-pair via truncation, lo-pair via rn)
__device__ __forceinline__ void split_pair(float f0, float f1, uint32_t& hi, uint32_t& lo) {
    hi = prmt_(__float_as_uint(f0), __float_as_uint(f1), 0x7632);
    float h0 = __uint_as_float(__float_as_uint(f0) & 0xffff0000u);
    float h1 = __uint_as_float(__float_as_uint(f1) & 0xffff0000u);
    lo = cvt_bf16x2_(f1 - h1, f0 - h0);
}
__device__ __forceinline__ float ex2f_(float x) {
    float y; asm("ex2.approx.f32 %0, %1;" : "=f"(y) : "f"(x)); return y;
}

__device__ __forceinline__ void mma16(float* c,
                                      uint32_t a0, uint32_t a1, uint32_t a2, uint32_t a3,
                                      uint32_t b0, uint32_t b1) {
    asm volatile(
        "mma.sync.aligned.m16n8k16.row.col.f32.bf16.bf16.f32 "
        "{%0,%1,%2,%3}, {%4,%5,%6,%7}, {%8,%9}, {%0,%1,%2,%3};"
        : "+f"(c[0]), "+f"(c[1]), "+f"(c[2]), "+f"(c[3])
        : "r"(a0), "r"(a1), "r"(a2), "r"(a3), "r"(b0), "r"(b1));
}
// (ah+al) x (bh+bl) ~= ah*bh + al*bh + ah*bl   (al*bl ~2^-16 rel, dropped)
__device__ __forceinline__ void mma_split16(float* c, const uint32_t* ah, const uint32_t* al,
                                            uint32_t bh0, uint32_t bh1,
                                            uint32_t bl0, uint32_t bl1) {
    mma16(c, ah[0], ah[1], ah[2], ah[3], bh0, bh1);
    mma16(c, al[0], al[1], al[2], al[3], bh0, bh1);
    mma16(c, ah[0], ah[1], ah[2], ah[3], bl0, bl1);
}

// ---------------- kernel 1: q proj (scaled) + W transpose/pack ----------------
__global__ void prep_kernel(const float* __restrict__ queries,
                            const float* __restrict__ Wq,
                            const float* __restrict__ Wk,
                            const float* __restrict__ Wv) {
    __shared__ float srow[D_];
    int bx = blockIdx.x, j = threadIdx.x;
    if (bx < B_) {
        for (int d = j; d < D_; d += 64) srow[d] = queries[bx * D_ + d];
        __syncthreads();
        float acc = 0.f;
#pragma unroll 8
        for (int d = 0; d < D_; d++) acc = fmaf(srow[d], Wq[d * KQ_ + j], acc);
        g_q_pk[bx * KQ_ + j] = pack_split(acc * QSCALE);
    } else {
        int idx0 = (bx - B_) * 512 + j;     // 64 blocks x 512 elems
#pragma unroll
        for (int t = 0; t < 8; t++) {
            int idx = idx0 + t * 64;
            int sel = idx >> 14;            // 0 = Wk, 1 = Wv (16384 elems each)
            int r = (idx >> 6) & 255;       // d
            int c = idx & 63;               // out col
            const float* W = sel ? Wv : Wk;
            g_wt_pk[sel][c][r] = pack_split(W[r * KQ_ + c]);
        }
    }
}

// ---------------- kernel 2: K/V projection, no smem, direct-LDG fragments -----
// [128 rows x 256] @ [256 x 64] per CTA. 8 warps = 4(m) x 2(n), warp 32x32.
__global__ __launch_bounds__(256, 2)
void proj_kernel(const float* __restrict__ keys, const float* __restrict__ values) {
    const float* in = blockIdx.y ? values : keys;
    uint32_t* out   = blockIdx.y ? g_v_pk : g_k_pk;
    const uint32_t* wt = &g_wt_pk[blockIdx.y][0][0];

    size_t rowbase = (size_t)blockIdx.x * 128;
    int tid = threadIdx.x, w = tid >> 5, lane = tid & 31;
    int gi = lane >> 2, ti = lane & 3;
    int m0 = (w >> 1) << 5, n0 = (w & 1) << 5;

    float c[2][4][4];
#pragma unroll
    for (int mf = 0; mf < 2; mf++)
#pragma unroll
        for (int nf = 0; nf < 4; nf++)
#pragma unroll
            for (int i = 0; i < 4; i++) c[mf][nf][i] = 0.f;

#pragma unroll 2
    for (int ks = 0; ks < 16; ks++) {
        int k0 = ks << 4;
        uint32_t ah[2][4], al[2][4];
#pragma unroll
        for (int mf = 0; mf < 2; mf++) {
            const float* ab = in + (rowbase + m0 + mf * 16 + gi) * D_ + k0 + 2 * ti;
            float2 f00 = *(const float2*)(ab);
            float2 f01 = *(const float2*)(ab + 8);
            float2 f10 = *(const float2*)(ab + 8 * D_);
            float2 f11 = *(const float2*)(ab + 8 * D_ + 8);
            split_pair(f00.x, f00.y, ah[mf][0], al[mf][0]);
            split_pair(f10.x, f10.y, ah[mf][1], al[mf][1]);
            split_pair(f01.x, f01.y, ah[mf][2], al[mf][2]);
            split_pair(f11.x, f11.y, ah[mf][3], al[mf][3]);
        }
#pragma unroll
        for (int nf = 0; nf < 4; nf++) {
            const uint32_t* bb = wt + (n0 + nf * 8 + gi) * D_ + k0 + 2 * ti;
            uint32_t bh0, bl0, bh1, bl1;
            unpack_pair(*(const uint2*)bb,       bh0, bl0);
            unpack_pair(*(const uint2*)(bb + 8), bh1, bl1);
#pragma unroll
            for (int mf = 0; mf < 2; mf++)
                mma_split16(c[mf][nf], ah[mf], al[mf], bh0, bh1, bl0, bl1);
        }
    }

#pragma unroll
    for (int mf = 0; mf < 2; mf++)
#pragma unroll
        for (int nf = 0; nf < 4; nf++) {
            size_t row = rowbase + m0 + mf * 16 + gi;
            int col = n0 + nf * 8 + 2 * ti;
            uint2 w0 = make_uint2(pack_split(c[mf][nf][0]), pack_split(c[mf][nf][1]));
            uint2 w1 = make_uint2(pack_split(c[mf][nf][2]), pack_split(c[mf][nf][3]));
            *(uint2*)(out + row * KQ_ + col)       = w0;
            *(uint2*)(out + (row + 8) * KQ_ + col) = w1;
        }
}

// ---------------- kernel 3: fused logits + softmax + attn@v -------------------
// block = (n, 32 b-rows). Only smem: S [32][1028] (fp32 -> packed-P in place).
#define SSTRW 1028

__global__ __launch_bounds__(256)
void attn_kernel(float* __restrict__ resOut, float* __restrict__ attnOut) {
    extern __shared__ float sm[];
    float* sS   = sm;                 // [32][SSTRW]
    float* sInv = sm + 32 * SSTRW;    // [32]

    int n  = blockIdx.y;
    int b0 = blockIdx.x * 32;
    int tid = threadIdx.x, w = tid >> 5, lane = tid & 31;
    int gi = lane >> 2, ti = lane & 3;

    // ---- Q fragments for all 4 k-steps, resident in registers ----
    uint32_t qh[4][2][4], ql[4][2][4];
#pragma unroll
    for (int ks = 0; ks < 4; ks++)
#pragma unroll
        for (int mf = 0; mf < 2; mf++) {
            const uint32_t* qb = g_q_pk + (b0 + mf * 16 + gi) * KQ_ + ks * 16 + 2 * ti;
            unpack_pair(*(const uint2*)qb,                qh[ks][mf][0], ql[ks][mf][0]);
            unpack_pair(*(const uint2*)(qb + 8 * KQ_),    qh[ks][mf][1], ql[ks][mf][1]);
            unpack_pair(*(const uint2*)(qb + 8),          qh[ks][mf][2], ql[ks][mf][2]);
            unpack_pair(*(const uint2*)(qb + 8 * KQ_ + 8), qh[ks][mf][3], ql[ks][mf][3]);
        }

    // ---- phase 1: S = Q @ K^T, K fragments straight from gmem ----
    const uint32_t* kbase = g_k_pk + (size_t)n * L_ * KQ_;
#pragma unroll 1
    for (int outer = 0; outer < 8; outer++) {
        int lc0 = outer * 128 + w * 16;
        float c[2][2][4];
#pragma unroll
        for (int mf = 0; mf < 2; mf++)
#pragma unroll
            for (int nf = 0; nf < 2; nf++)
#pragma unroll
                for (int i = 0; i < 4; i++) c[mf][nf][i] = 0.f;

#pragma unroll
        for (int ks = 0; ks < 4; ks++) {
#pragma unroll
            for (int nf = 0; nf < 2; nf++) {
                const uint32_t* bb = kbase + (size_t)(lc0 + nf * 8 + gi) * KQ_ + ks * 16 + 2 * ti;
                uint32_t bh0, bl0, bh1, bl1;
                unpack_pair(*(const uint2*)bb,       bh0, bl0);
                unpack_pair(*(const uint2*)(bb + 8), bh1, bl1);
                mma_split16(c[0][nf], qh[ks][0], ql[ks][0], bh0, bh1, bl0, bl1);
                mma_split16(c[1][nf], qh[ks][1], ql[ks][1], bh0, bh1, bl0, bl1);
            }
        }
#pragma unroll
        for (int mf = 0; mf < 2; mf++)
#pragma unroll
            for (int nf = 0; nf < 2; nf++) {
                int row = mf * 16 + gi;
                int col = lc0 + nf * 8 + 2 * ti;
                *(float2*)(sS + row * SSTRW + col)       = make_float2(c[mf][nf][0], c[mf][nf][1]);
                *(float2*)(sS + (row + 8) * SSTRW + col) = make_float2(c[mf][nf][2], c[mf][nf][3]);
            }
    }
    __syncthreads();

    // ---- phase 2: softmax (exp2 domain); repack P as bf16-split in place ----
#pragma unroll 1
    for (int rr = 0; rr < 4; rr++) {
        int r = w * 4 + rr;
        float* srow = sS + r * SSTRW;
        float m = -3.402823466e38f;
#pragma unroll 8
        for (int j = 0; j < 32; j++) m = fmaxf(m, srow[j * 32 + lane]);
#pragma unroll
        for (int d = 16; d >= 1; d >>= 1) m = fmaxf(m, __shfl_xor_sync(0xffffffffu, m, d));
        float s = 0.f;
#pragma unroll 8
        for (int j = 0; j < 32; j++) {
            float e = ex2f_(srow[j * 32 + lane] - m);
            srow[j * 32 + lane] = e;
            s += e;
        }
#pragma unroll
        for (int d = 16; d >= 1; d >>= 1) s += __shfl_xor_sync(0xffffffffu, s, d);
        float inv = 1.0f / s;
        float* arow = attnOut + ((size_t)n * B_ + b0 + r) * L_;
        uint32_t* urow = (uint32_t*)srow;
#pragma unroll 8
        for (int j = 0; j < 32; j++) {
            float e = srow[j * 32 + lane];
            arow[j * 32 + lane] = e * inv;
            urow[j * 32 + lane] = pack_split(e);
        }
        if (lane == 0) sInv[r] = inv;
    }
    __syncthreads();

    // ---- phase 3: out = P @ V, V fragments straight from gmem ----
    const uint32_t* vbase = g_v_pk + (size_t)n * L_ * OUT_;
    const uint32_t* sSu = (const uint32_t*)sS;
    float acc[2][2][4];
#pragma unroll
    for (int p = 0; p < 2; p++)
#pragma unroll
        for (int mf = 0; mf < 2; mf++)
#pragma unroll
            for (int i = 0; i < 4; i++) acc[p][mf][i] = 0.f;

#pragma unroll 2
    for (int ls = 0; ls < 64; ls++) {
        int l0 = ls << 4;
        uint32_t ah[2][4], al[2][4];
#pragma unroll
        for (int mf = 0; mf < 2; mf++) {
            const uint32_t* ab = sSu + (mf * 16 + gi) * SSTRW + l0 + 2 * ti;
            unpack_pair(*(const uint2*)ab,                  ah[mf][0], al[mf][0]);
            unpack_pair(*(const uint2*)(ab + 8 * SSTRW),    ah[mf][1], al[mf][1]);
            unpack_pair(*(const uint2*)(ab + 8),            ah[mf][2], al[mf][2]);
            unpack_pair(*(const uint2*)(ab + 8 * SSTRW + 8), ah[mf][3], al[mf][3]);
        }
        const uint32_t* vb = vbase + (size_t)(l0 + 2 * ti) * OUT_ + w * 8 + gi;
        uint32_t v00 = vb[0], v01 = vb[OUT_], v10 = vb[8 * OUT_], v11 = vb[9 * OUT_];
        uint32_t bh0 = prmt_(v00, v01, 0x7632), bl0 = prmt_(v00, v01, 0x5410);
        uint32_t bh1 = prmt_(v10, v11, 0x7632), bl1 = prmt_(v10, v11, 0x5410);
        float* a0 = acc[ls & 1][0];
        float* a1 = acc[ls & 1][1];
        mma_split16(a0, ah[0], al[0], bh0, bh1, bl0, bl1);
        mma_split16(a1, ah[1], al[1], bh0, bh1, bl0, bl1);
    }

#pragma unroll
    for (int mf = 0; mf < 2; mf++) {
        int row = mf * 16 + gi;
        float i0 = sInv[row], i1 = sInv[row + 8];
        float c0 = acc[0][mf][0] + acc[1][mf][0];
        float c1 = acc[0][mf][1] + acc[1][mf][1];
        float c2 = acc[0][mf][2] + acc[1][mf][2];
        float c3 = acc[0][mf][3] + acc[1][mf][3];
        float* op0 = resOut + ((size_t)(b0 + row) * N_ + n) * OUT_ + w * 8 + 2 * ti;
        float* op1 = resOut + ((size_t)(b0 + row + 8) * N_ + n) * OUT_ + w * 8 + 2 * ti;
        *(float2*)op0 = make_float2(c0 * i0, c1 * i0);
        *(float2*)op1 = make_float2(c2 * i1, c3 * i1);
    }
}

// ----------------------------- launcher --------------------------------------
extern "C" void kernel_launch(void* const* d_in, const int* in_sizes, int n_in,
                              void* d_out, int out_size) {
    const float* queries = (const float*)d_in[0];
    const float* keys    = (const float*)d_in[1];
    const float* values  = (const float*)d_in[2];
    const float* Wq      = (const float*)d_in[3];
    const float* Wk      = (const float*)d_in[4];
    const float* Wv      = (const float*)d_in[5];

    float* resOut  = (float*)d_out;                      // [B, N, OUT]
    float* attnOut = resOut + (size_t)B_ * N_ * OUT_;    // [N, B, L]

    const int SMEM_ATTN = (32 * SSTRW + 32) * (int)sizeof(float);  // ~129 KB
    cudaFuncSetAttribute(attn_kernel, cudaFuncAttributeMaxDynamicSharedMemorySize, SMEM_ATTN);

    prep_kernel<<<B_ + 64, 64>>>(queries, Wq, Wk, Wv);
    proj_kernel<<<dim3((N_ * L_) / 128, 2), 256>>>(keys, values);
    attn_kernel<<<dim3(B_ / 32, N_), 256, SMEM_ATTN>>>(resOut, attnOut);
}

// round 13
// speedup vs baseline: 3.3869x; 1.1840x over previous
#include <cuda_runtime.h>
#include <cstdint>
#include <cstddef>

#define B_    256
#define N_    256
#define L_    1024
#define D_    256
#define KQ_   64
#define OUT_  64

// 0.125 (=1/sqrt(KQ)) * log2(e): softmax computed in exp2 domain
#define QSCALE 0.18033688011112042f

// ---------------- scratch (device globals: allocation-free rule) -------------
// packed format: u32 = (bf16(hi) << 16) | bf16(lo),  value ~= hi + lo
__device__ uint32_t g_q_pk[B_ * KQ_];                       // scaled q
__device__ uint32_t g_k_pk[(size_t)N_ * L_ * KQ_];          // 64 MB
__device__ uint32_t g_v_pk[(size_t)N_ * L_ * OUT_];         // 64 MB
__device__ uint32_t g_wt_pk[2][KQ_][D_];                    // Wk^T, Wv^T packed

// ---------------- bf16-split helpers ------------------------------------------
__device__ __forceinline__ uint32_t prmt_(uint32_t a, uint32_t b, uint32_t sel) {
    uint32_t d; asm("prmt.b32 %0, %1, %2, %3;" : "=r"(d) : "r"(a), "r"(b), "r"(sel));
    return d;
}
__device__ __forceinline__ uint32_t cvt_bf16x2_(float hi_arg, float lo_arg) {
    // d<31:16> = bf16(hi_arg), d<15:0> = bf16(lo_arg)
    uint32_t d; asm("cvt.rn.bf16x2.f32 %0, %1, %2;" : "=r"(d) : "f"(hi_arg), "f"(lo_arg));
    return d;
}
// pack fp32 f -> (trunc-bf16 hi in high16, rn-bf16 of residual in low16)
__device__ __forceinline__ uint32_t pack_split(float f) {
    float hif = __uint_as_float(__float_as_uint(f) & 0xffff0000u);
    float lo  = f - hif;
    uint32_t t = cvt_bf16x2_(lo, lo);
    return prmt_(t, __float_as_uint(f), 0x7610);   // {t.b0,t.b1,f.b2,f.b3}
}
// two packed words (elem j, j+1) -> mma bf16x2 regs (hi-pair, lo-pair)
__device__ __forceinline__ void unpack_pair(uint2 w, uint32_t& hi, uint32_t& lo) {
    hi = prmt_(w.x, w.y, 0x7632);
    lo = prmt_(w.x, w.y, 0x5410);
}
// two fp32 -> split pair regs (hi-pair via truncation, lo-pair via rn)
__device__ __forceinline__ void split_pair(float f0, float f1, uint32_t& hi, uint32_t& lo) {
    hi = prmt_(__float_as_uint(f0), __float_as_uint(f1), 0x7632);
    float h0 = __uint_as_float(__float_as_uint(f0) & 0xffff0000u);
    float h1 = __uint_as_float(__float_as_uint(f1) & 0xffff0000u);
    lo = cvt_bf16x2_(f1 - h1, f0 - h0);
}
__device__ __forceinline__ float ex2f_(float x) {
    float y; asm("ex2.approx.f32 %0, %1;" : "=f"(y) : "f"(x)); return y;
}

__device__ __forceinline__ void mma16(float* c,
                                      uint32_t a0, uint32_t a1, uint32_t a2, uint32_t a3,
                                      uint32_t b0, uint32_t b1) {
    asm volatile(
        "mma.sync.aligned.m16n8k16.row.col.f32.bf16.bf16.f32 "
        "{%0,%1,%2,%3}, {%4,%5,%6,%7}, {%8,%9}, {%0,%1,%2,%3};"
        : "+f"(c[0]), "+f"(c[1]), "+f"(c[2]), "+f"(c[3])
        : "r"(a0), "r"(a1), "r"(a2), "r"(a3), "r"(b0), "r"(b1));
}
// (ah+al) x (bh+bl) ~= ah*bh + al*bh + ah*bl   (al*bl ~2^-16 rel, dropped)
__device__ __forceinline__ void mma_split16(float* c, const uint32_t* ah, const uint32_t* al,
                                            uint32_t bh0, uint32_t bh1,
                                            uint32_t bl0, uint32_t bl1) {
    mma16(c, ah[0], ah[1], ah[2], ah[3], bh0, bh1);
    mma16(c, al[0], al[1], al[2], al[3], bh0, bh1);
    mma16(c, ah[0], ah[1], ah[2], ah[3], bl0, bl1);
}

// ---------------- kernel 1: q proj (scaled) + W transpose/pack ----------------
__global__ void prep_kernel(const float* __restrict__ queries,
                            const float* __restrict__ Wq,
                            const float* __restrict__ Wk,
                            const float* __restrict__ Wv) {
    __shared__ float srow[D_];
    int bx = blockIdx.x, j = threadIdx.x;
    if (bx < B_) {
        for (int d = j; d < D_; d += 64) srow[d] = queries[bx * D_ + d];
        __syncthreads();
        float acc = 0.f;
#pragma unroll 8
        for (int d = 0; d < D_; d++) acc = fmaf(srow[d], Wq[d * KQ_ + j], acc);
        g_q_pk[bx * KQ_ + j] = pack_split(acc * QSCALE);
    } else {
        int idx0 = (bx - B_) * 512 + j;     // 64 blocks x 512 elems
#pragma unroll
        for (int t = 0; t < 8; t++) {
            int idx = idx0 + t * 64;
            int sel = idx >> 14;            // 0 = Wk, 1 = Wv (16384 elems each)
            int r = (idx >> 6) & 255;       // d
            int c = idx & 63;               // out col
            const float* W = sel ? Wv : Wk;
            g_wt_pk[sel][c][r] = pack_split(W[r * KQ_ + c]);
        }
    }
}

// ---------------- kernel 2: K/V projection, no smem, direct-LDG fragments -----
// [128 rows x 256] @ [256 x 64] per CTA. 8 warps = 4(m) x 2(n), warp 32x32.
__global__ __launch_bounds__(256, 2)
void proj_kernel(const float* __restrict__ keys, const float* __restrict__ values) {
    const float* in = blockIdx.y ? values : keys;
    uint32_t* out   = blockIdx.y ? g_v_pk : g_k_pk;
    const uint32_t* wt = &g_wt_pk[blockIdx.y][0][0];

    size_t rowbase = (size_t)blockIdx.x * 128;
    int tid = threadIdx.x, w = tid >> 5, lane = tid & 31;
    int gi = lane >> 2, ti = lane & 3;
    int m0 = (w >> 1) << 5, n0 = (w & 1) << 5;

    float c[2][4][4];
#pragma unroll
    for (int mf = 0; mf < 2; mf++)
#pragma unroll
        for (int nf = 0; nf < 4; nf++)
#pragma unroll
            for (int i = 0; i < 4; i++) c[mf][nf][i] = 0.f;

#pragma unroll 2
    for (int ks = 0; ks < 16; ks++) {
        int k0 = ks << 4;
        uint32_t ah[2][4], al[2][4];
#pragma unroll
        for (int mf = 0; mf < 2; mf++) {
            const float* ab = in + (rowbase + m0 + mf * 16 + gi) * D_ + k0 + 2 * ti;
            float2 f00 = *(const float2*)(ab);
            float2 f01 = *(const float2*)(ab + 8);
            float2 f10 = *(const float2*)(ab + 8 * D_);
            float2 f11 = *(const float2*)(ab + 8 * D_ + 8);
            split_pair(f00.x, f00.y, ah[mf][0], al[mf][0]);
            split_pair(f10.x, f10.y, ah[mf][1], al[mf][1]);
            split_pair(f01.x, f01.y, ah[mf][2], al[mf][2]);
            split_pair(f11.x, f11.y, ah[mf][3], al[mf][3]);
        }
#pragma unroll
        for (int nf = 0; nf < 4; nf++) {
            const uint32_t* bb = wt + (n0 + nf * 8 + gi) * D_ + k0 + 2 * ti;
            uint32_t bh0, bl0, bh1, bl1;
            unpack_pair(*(const uint2*)bb,       bh0, bl0);
            unpack_pair(*(const uint2*)(bb + 8), bh1, bl1);
#pragma unroll
            for (int mf = 0; mf < 2; mf++)
                mma_split16(c[mf][nf], ah[mf], al[mf], bh0, bh1, bl0, bl1);
        }
    }

#pragma unroll
    for (int mf = 0; mf < 2; mf++)
#pragma unroll
        for (int nf = 0; nf < 4; nf++) {
            size_t row = rowbase + m0 + mf * 16 + gi;
            int col = n0 + nf * 8 + 2 * ti;
            uint2 w0 = make_uint2(pack_split(c[mf][nf][0]), pack_split(c[mf][nf][1]));
            uint2 w1 = make_uint2(pack_split(c[mf][nf][2]), pack_split(c[mf][nf][3]));
            *(uint2*)(out + row * KQ_ + col)       = w0;
            *(uint2*)(out + (row + 8) * KQ_ + col) = w1;
        }
}

// ---------------- kernel 3: fused logits + softmax + attn@v -------------------
// block = (n, 16 b-rows). smem: S [16][1028] only -> 66 KB -> 3 CTAs/SM.
#define ROWS_A 16
#define SSTRW  1028

__global__ __launch_bounds__(256, 3)
void attn_kernel(float* __restrict__ resOut, float* __restrict__ attnOut) {
    extern __shared__ float sm[];
    float* sS   = sm;                     // [16][SSTRW]
    float* sInv = sm + ROWS_A * SSTRW;    // [16]

    int n  = blockIdx.y;
    int b0 = blockIdx.x * ROWS_A;
    int tid = threadIdx.x, w = tid >> 5, lane = tid & 31;
    int gi = lane >> 2, ti = lane & 3;

    // ---- Q fragments (16 rows) for all 4 k-steps, register-resident ----
    uint32_t qh[4][4], ql[4][4];
#pragma unroll
    for (int ks = 0; ks < 4; ks++) {
        const uint32_t* qb = g_q_pk + (b0 + gi) * KQ_ + ks * 16 + 2 * ti;
        unpack_pair(*(const uint2*)qb,                 qh[ks][0], ql[ks][0]);
        unpack_pair(*(const uint2*)(qb + 8 * KQ_),     qh[ks][1], ql[ks][1]);
        unpack_pair(*(const uint2*)(qb + 8),           qh[ks][2], ql[ks][2]);
        unpack_pair(*(const uint2*)(qb + 8 * KQ_ + 8), qh[ks][3], ql[ks][3]);
    }

    // ---- phase 1: S = Q @ K^T, K fragments straight from gmem ----
    const uint32_t* kbase = g_k_pk + (size_t)n * L_ * KQ_;
#pragma unroll 1
    for (int outer = 0; outer < 8; outer++) {
        int lc0 = outer * 128 + w * 16;
        float c[2][4];
#pragma unroll
        for (int nf = 0; nf < 2; nf++)
#pragma unroll
            for (int i = 0; i < 4; i++) c[nf][i] = 0.f;

#pragma unroll
        for (int ks = 0; ks < 4; ks++) {
#pragma unroll
            for (int nf = 0; nf < 2; nf++) {
                const uint32_t* bb = kbase + (size_t)(lc0 + nf * 8 + gi) * KQ_ + ks * 16 + 2 * ti;
                uint32_t bh0, bl0, bh1, bl1;
                unpack_pair(*(const uint2*)bb,       bh0, bl0);
                unpack_pair(*(const uint2*)(bb + 8), bh1, bl1);
                mma_split16(c[nf], qh[ks], ql[ks], bh0, bh1, bl0, bl1);
            }
        }
#pragma unroll
        for (int nf = 0; nf < 2; nf++) {
            int col = lc0 + nf * 8 + 2 * ti;
            *(float2*)(sS + gi * SSTRW + col)       = make_float2(c[nf][0], c[nf][1]);
            *(float2*)(sS + (gi + 8) * SSTRW + col) = make_float2(c[nf][2], c[nf][3]);
        }
    }
    __syncthreads();

    // ---- phase 2: softmax (exp2 domain); repack P as bf16-split in place ----
#pragma unroll 1
    for (int rr = 0; rr < 2; rr++) {
        int r = w * 2 + rr;
        float* srow = sS + r * SSTRW;
        float m = -3.402823466e38f;
#pragma unroll 8
        for (int j = 0; j < 32; j++) m = fmaxf(m, srow[j * 32 + lane]);
#pragma unroll
        for (int d = 16; d >= 1; d >>= 1) m = fmaxf(m, __shfl_xor_sync(0xffffffffu, m, d));
        float s = 0.f;
#pragma unroll 8
        for (int j = 0; j < 32; j++) {
            float e = ex2f_(srow[j * 32 + lane] - m);
            srow[j * 32 + lane] = e;
            s += e;
        }
#pragma unroll
        for (int d = 16; d >= 1; d >>= 1) s += __shfl_xor_sync(0xffffffffu, s, d);
        float inv = 1.0f / s;
        float* arow = attnOut + ((size_t)n * B_ + b0 + r) * L_;
        uint32_t* urow = (uint32_t*)srow;
#pragma unroll 8
        for (int j = 0; j < 32; j++) {
            float e = srow[j * 32 + lane];
            arow[j * 32 + lane] = e * inv;
            urow[j * 32 + lane] = pack_split(e);
        }
        if (lane == 0) sInv[r] = inv;
    }
    __syncthreads();

    // ---- phase 3: out = P @ V, V fragments straight from gmem ----
    const uint32_t* vbase = g_v_pk + (size_t)n * L_ * OUT_;
    const uint32_t* sSu = (const uint32_t*)sS;
    float acc[2][4];
#pragma unroll
    for (int p = 0; p < 2; p++)
#pragma unroll
        for (int i = 0; i < 4; i++) acc[p][i] = 0.f;

#pragma unroll 2
    for (int ls = 0; ls < 64; ls++) {
        int l0 = ls << 4;
        uint32_t ah[4], al[4];
        const uint32_t* ab = sSu + gi * SSTRW + l0 + 2 * ti;
        unpack_pair(*(const uint2*)ab,                   ah[0], al[0]);
        unpack_pair(*(const uint2*)(ab + 8 * SSTRW),     ah[1], al[1]);
        unpack_pair(*(const uint2*)(ab + 8),             ah[2], al[2]);
        unpack_pair(*(const uint2*)(ab + 8 * SSTRW + 8), ah[3], al[3]);

        const uint32_t* vb = vbase + (size_t)(l0 + 2 * ti) * OUT_ + w * 8 + gi;
        uint32_t v00 = vb[0], v01 = vb[OUT_], v10 = vb[8 * OUT_], v11 = vb[9 * OUT_];
        uint32_t bh0 = prmt_(v00, v01, 0x7632), bl0 = prmt_(v00, v01, 0x5410);
        uint32_t bh1 = prmt_(v10, v11, 0x7632), bl1 = prmt_(v10, v11, 0x5410);
        mma_split16(acc[ls & 1], ah, al, bh0, bh1, bl0, bl1);
    }

    // epilogue: scale by 1/rowsum, store result [B][N][64]
    {
        float i0 = sInv[gi], i1 = sInv[gi + 8];
        float c0 = acc[0][0] + acc[1][0];
        float c1 = acc[0][1] + acc[1][1];
        float c2 = acc[0][2] + acc[1][2];
        float c3 = acc[0][3] + acc[1][3];
        float* op0 = resOut + ((size_t)(b0 + gi) * N_ + n) * OUT_ + w * 8 + 2 * ti;
        float* op1 = resOut + ((size_t)(b0 + gi + 8) * N_ + n) * OUT_ + w * 8 + 2 * ti;
        *(float2*)op0 = make_float2(c0 * i0, c1 * i0);
        *(float2*)op1 = make_float2(c2 * i1, c3 * i1);
    }
}

// ----------------------------- launcher --------------------------------------
extern "C" void kernel_launch(void* const* d_in, const int* in_sizes, int n_in,
                              void* d_out, int out_size) {
    const float* queries = (const float*)d_in[0];
    const float* keys    = (const float*)d_in[1];
    const float* values  = (const float*)d_in[2];
    const float* Wq      = (const float*)d_in[3];
    const float* Wk      = (const float*)d_in[4];
    const float* Wv      = (const float*)d_in[5];

    float* resOut  = (float*)d_out;                      // [B, N, OUT]
    float* attnOut = resOut + (size_t)B_ * N_ * OUT_;    // [N, B, L]

    const int SMEM_ATTN = (ROWS_A * SSTRW + 16) * (int)sizeof(float);  // ~66 KB
    cudaFuncSetAttribute(attn_kernel, cudaFuncAttributeMaxDynamicSharedMemorySize, SMEM_ATTN);

    prep_kernel<<<B_ + 64, 64>>>(queries, Wq, Wk, Wv);
    proj_kernel<<<dim3((N_ * L_) / 128, 2), 256>>>(keys, values);
    attn_kernel<<<dim3(B_ / ROWS_A, N_), 256, SMEM_ATTN>>>(resOut, attnOut);
}

// round 15
// speedup vs baseline: 3.4507x; 1.0188x over previous
#include <cuda_runtime.h>
#include <cstdint>
#include <cstddef>

#define B_    256
#define N_    256
#define L_    1024
#define D_    256
#define KQ_   64
#define OUT_  64

// 0.125 (=1/sqrt(KQ)) * log2(e): softmax computed in exp2 domain
#define QSCALE 0.18033688011112042f

// ---------------- scratch (device globals: allocation-free rule) -------------
// packed format: u32 = (bf16(hi) << 16) | bf16(lo),  value ~= hi + lo
__device__ uint32_t g_q_pk[B_ * KQ_];                       // scaled q
__device__ uint32_t g_k_pk[(size_t)N_ * L_ * KQ_];          // 64 MB
__device__ uint32_t g_v_pk[(size_t)N_ * L_ * OUT_];         // 64 MB
__device__ uint32_t g_wt_pk[2][KQ_][D_];                    // Wk^T, Wv^T packed

// ---------------- bf16-split helpers ------------------------------------------
__device__ __forceinline__ uint32_t prmt_(uint32_t a, uint32_t b, uint32_t sel) {
    uint32_t d; asm("prmt.b32 %0, %1, %2, %3;" : "=r"(d) : "r"(a), "r"(b), "r"(sel));
    return d;
}
__device__ __forceinline__ uint32_t cvt_bf16x2_(float hi_arg, float lo_arg) {
    uint32_t d; asm("cvt.rn.bf16x2.f32 %0, %1, %2;" : "=r"(d) : "f"(hi_arg), "f"(lo_arg));
    return d;
}
// pack fp32 f -> (trunc-bf16 hi in high16, rn-bf16 of residual in low16)
__device__ __forceinline__ uint32_t pack_split(float f) {
    float hif = __uint_as_float(__float_as_uint(f) & 0xffff0000u);
    float lo  = f - hif;
    uint32_t t = cvt_bf16x2_(lo, lo);
    return prmt_(t, __float_as_uint(f), 0x7610);   // {t.b0,t.b1,f.b2,f.b3}
}
// two packed words (elem j, j+1) -> mma bf16x2 regs (hi-pair, lo-pair)
__device__ __forceinline__ void unpack_pair(uint2 w, uint32_t& hi, uint32_t& lo) {
    hi = prmt_(w.x, w.y, 0x7632);
    lo = prmt_(w.x, w.y, 0x5410);
}
// two fp32 -> split pair regs (hi-pair via truncation, lo-pair via rn)
__device__ __forceinline__ void split_pair(float f0, float f1, uint32_t& hi, uint32_t& lo) {
    hi = prmt_(__float_as_uint(f0), __float_as_uint(f1), 0x7632);
    float h0 = __uint_as_float(__float_as_uint(f0) & 0xffff0000u);
    float h1 = __uint_as_float(__float_as_uint(f1) & 0xffff0000u);
    lo = cvt_bf16x2_(f1 - h1, f0 - h0);
}
__device__ __forceinline__ float ex2f_(float x) {
    float y; asm("ex2.approx.f32 %0, %1;" : "=f"(y) : "f"(x)); return y;
}
// pinned-issue global loads (volatile: compiler cannot sink past uses/barriers)
__device__ __forceinline__ uint32_t ldg_u32(const uint32_t* p) {
    uint32_t v; asm volatile("ld.global.nc.b32 %0, [%1];" : "=r"(v) : "l"(p)); return v;
}
__device__ __forceinline__ uint2 ldg_u64(const uint32_t* p) {
    uint2 v; asm volatile("ld.global.nc.v2.b32 {%0,%1}, [%2];" : "=r"(v.x), "=r"(v.y) : "l"(p));
    return v;
}

__device__ __forceinline__ void mma16(float* c,
                                      uint32_t a0, uint32_t a1, uint32_t a2, uint32_t a3,
                                      uint32_t b0, uint32_t b1) {
    asm volatile(
        "mma.sync.aligned.m16n8k16.row.col.f32.bf16.bf16.f32 "
        "{%0,%1,%2,%3}, {%4,%5,%6,%7}, {%8,%9}, {%0,%1,%2,%3};"
        : "+f"(c[0]), "+f"(c[1]), "+f"(c[2]), "+f"(c[3])
        : "r"(a0), "r"(a1), "r"(a2), "r"(a3), "r"(b0), "r"(b1));
}
// (ah+al) x (bh+bl) ~= ah*bh + al*bh + ah*bl   (al*bl ~2^-16 rel, dropped)
__device__ __forceinline__ void mma_split16(float* c, const uint32_t* ah, const uint32_t* al,
                                            uint32_t bh0, uint32_t bh1,
                                            uint32_t bl0, uint32_t bl1) {
    mma16(c, ah[0], ah[1], ah[2], ah[3], bh0, bh1);
    mma16(c, al[0], al[1], al[2], al[3], bh0, bh1);
    mma16(c, ah[0], ah[1], ah[2], ah[3], bl0, bl1);
}

// ---------------- kernel 1: q proj (scaled) + W transpose/pack ----------------
__global__ __launch_bounds__(256)
void prep_kernel(const float* __restrict__ queries,
                 const float* __restrict__ Wq,
                 const float* __restrict__ Wk,
                 const float* __restrict__ Wv) {
    __shared__ float sred[4][64];
    int bx = blockIdx.x, tid = threadIdx.x;
    if (bx < B_) {
        int j = tid & 63, sl = tid >> 6;
        const float* qrow = queries + bx * D_;
        float acc = 0.f;
#pragma unroll 16
        for (int d = sl * 64; d < sl * 64 + 64; d++)
            acc = fmaf(qrow[d], Wq[d * KQ_ + j], acc);
        sred[sl][j] = acc;
        __syncthreads();
        if (sl == 0) {
            float a = sred[0][j] + sred[1][j] + sred[2][j] + sred[3][j];
            g_q_pk[bx * KQ_ + j] = pack_split(a * QSCALE);
        }
    } else {
        int idx0 = (bx - B_) * 512 + tid;   // 64 blocks x 512 elems
#pragma unroll
        for (int t = 0; t < 2; t++) {
            int idx = idx0 + t * 256;
            int sel = idx >> 14;            // 0 = Wk, 1 = Wv
            int r = (idx >> 6) & 255;       // d
            int c = idx & 63;               // out col
            const float* W = sel ? Wv : Wk;
            g_wt_pk[sel][c][r] = pack_split(W[r * KQ_ + c]);
        }
    }
}

// ---------------- kernel 2: K/V projection, no smem, direct-LDG fragments -----
__global__ __launch_bounds__(256, 2)
void proj_kernel(const float* __restrict__ keys, const float* __restrict__ values) {
    const float* in = blockIdx.y ? values : keys;
    uint32_t* out   = blockIdx.y ? g_v_pk : g_k_pk;
    const uint32_t* wt = &g_wt_pk[blockIdx.y][0][0];

    size_t rowbase = (size_t)blockIdx.x * 128;
    int tid = threadIdx.x, w = tid >> 5, lane = tid & 31;
    int gi = lane >> 2, ti = lane & 3;
    int m0 = (w >> 1) << 5, n0 = (w & 1) << 5;

    float c[2][4][4];
#pragma unroll
    for (int mf = 0; mf < 2; mf++)
#pragma unroll
        for (int nf = 0; nf < 4; nf++)
#pragma unroll
            for (int i = 0; i < 4; i++) c[mf][nf][i] = 0.f;

#pragma unroll 4
    for (int ks = 0; ks < 16; ks++) {
        int k0 = ks << 4;
        uint32_t ah[2][4], al[2][4];
#pragma unroll
        for (int mf = 0; mf < 2; mf++) {
            const float* ab = in + (rowbase + m0 + mf * 16 + gi) * D_ + k0 + 2 * ti;
            float2 f00 = *(const float2*)(ab);
            float2 f01 = *(const float2*)(ab + 8);
            float2 f10 = *(const float2*)(ab + 8 * D_);
            float2 f11 = *(const float2*)(ab + 8 * D_ + 8);
            split_pair(f00.x, f00.y, ah[mf][0], al[mf][0]);
            split_pair(f10.x, f10.y, ah[mf][1], al[mf][1]);
            split_pair(f01.x, f01.y, ah[mf][2], al[mf][2]);
            split_pair(f11.x, f11.y, ah[mf][3], al[mf][3]);
        }
#pragma unroll
        for (int nf = 0; nf < 4; nf++) {
            const uint32_t* bb = wt + (n0 + nf * 8 + gi) * D_ + k0 + 2 * ti;
            uint32_t bh0, bl0, bh1, bl1;
            unpack_pair(*(const uint2*)bb,       bh0, bl0);
            unpack_pair(*(const uint2*)(bb + 8), bh1, bl1);
#pragma unroll
            for (int mf = 0; mf < 2; mf++)
                mma_split16(c[mf][nf], ah[mf], al[mf], bh0, bh1, bl0, bl1);
        }
    }

#pragma unroll
    for (int mf = 0; mf < 2; mf++)
#pragma unroll
        for (int nf = 0; nf < 4; nf++) {
            size_t row = rowbase + m0 + mf * 16 + gi;
            int col = n0 + nf * 8 + 2 * ti;
            uint2 w0 = make_uint2(pack_split(c[mf][nf][0]), pack_split(c[mf][nf][1]));
            uint2 w1 = make_uint2(pack_split(c[mf][nf][2]), pack_split(c[mf][nf][3]));
            *(uint2*)(out + row * KQ_ + col)       = w0;
            *(uint2*)(out + (row + 8) * KQ_ + col) = w1;
        }
}

// ---------------- kernel 3: fused logits + softmax + attn@v -------------------
// block = (n, 16 b-rows). smem: S [16][1028] only -> 66 KB -> 3 CTAs/SM.
#define ROWS_A 16
#define SSTRW  1028

__global__ __launch_bounds__(256, 3)
void attn_kernel(float* __restrict__ resOut, float* __restrict__ attnOut) {
    extern __shared__ float sm[];
    float* sS   = sm;                     // [16][SSTRW]
    float* sInv = sm + ROWS_A * SSTRW;    // [16]

    int n  = blockIdx.y;
    int b0 = blockIdx.x * ROWS_A;
    int tid = threadIdx.x, w = tid >> 5, lane = tid & 31;
    int gi = lane >> 2, ti = lane & 3;

    // ---- Q fragments (16 rows) for all 4 k-steps, register-resident ----
    uint32_t qh[4][4], ql[4][4];
#pragma unroll
    for (int ks = 0; ks < 4; ks++) {
        const uint32_t* qb = g_q_pk + (b0 + gi) * KQ_ + ks * 16 + 2 * ti;
        unpack_pair(*(const uint2*)qb,                 qh[ks][0], ql[ks][0]);
        unpack_pair(*(const uint2*)(qb + 8 * KQ_),     qh[ks][1], ql[ks][1]);
        unpack_pair(*(const uint2*)(qb + 8),           qh[ks][2], ql[ks][2]);
        unpack_pair(*(const uint2*)(qb + 8 * KQ_ + 8), qh[ks][3], ql[ks][3]);
    }

    // ---- phase 1: S = Q @ K^T, K fragments pipelined from gmem ----
    const uint32_t* kbase = g_k_pk + (size_t)n * L_ * KQ_;
#pragma unroll 1
    for (int outer = 0; outer < 8; outer++) {
        int lc0 = outer * 128 + w * 16;
        const uint32_t* kb0 = kbase + (size_t)(lc0 + gi) * KQ_ + 2 * ti;  // nf=0 rows
        const uint32_t* kb1 = kb0 + 8 * KQ_;                               // nf=1 rows

        float c[2][4];
#pragma unroll
        for (int nf = 0; nf < 2; nf++)
#pragma unroll
            for (int i = 0; i < 4; i++) c[nf][i] = 0.f;

        uint2 kw[2][4];
        kw[0][0] = ldg_u64(kb0);
        kw[0][1] = ldg_u64(kb0 + 8);
        kw[0][2] = ldg_u64(kb1);
        kw[0][3] = ldg_u64(kb1 + 8);
#pragma unroll
        for (int ks = 0; ks < 4; ks++) {
            int cur = ks & 1, nxt = cur ^ 1;
            if (ks < 3) {   // prefetch next k-step before MMAs of this one
                const uint32_t* p0 = kb0 + (ks + 1) * 16;
                const uint32_t* p1 = kb1 + (ks + 1) * 16;
                kw[nxt][0] = ldg_u64(p0);
                kw[nxt][1] = ldg_u64(p0 + 8);
                kw[nxt][2] = ldg_u64(p1);
                kw[nxt][3] = ldg_u64(p1 + 8);
            }
            uint32_t bh0, bl0, bh1, bl1;
            unpack_pair(kw[cur][0], bh0, bl0);
            unpack_pair(kw[cur][1], bh1, bl1);
            mma_split16(c[0], qh[ks], ql[ks], bh0, bh1, bl0, bl1);
            unpack_pair(kw[cur][2], bh0, bl0);
            unpack_pair(kw[cur][3], bh1, bl1);
            mma_split16(c[1], qh[ks], ql[ks], bh0, bh1, bl0, bl1);
        }
#pragma unroll
        for (int nf = 0; nf < 2; nf++) {
            int col = lc0 + nf * 8 + 2 * ti;
            *(float2*)(sS + gi * SSTRW + col)       = make_float2(c[nf][0], c[nf][1]);
            *(float2*)(sS + (gi + 8) * SSTRW + col) = make_float2(c[nf][2], c[nf][3]);
        }
    }

    // ---- prefetch phase-3 V iteration 0 NOW (independent of the barrier);
    //      its L2/DRAM latency hides under the whole softmax phase ----
    const uint32_t* vbase = g_v_pk + (size_t)n * L_ * OUT_
                          + (size_t)(2 * ti) * OUT_ + w * 8 + gi;
    uint32_t vw[2][4];
    vw[0][0] = ldg_u32(vbase);
    vw[0][1] = ldg_u32(vbase + OUT_);
    vw[0][2] = ldg_u32(vbase + 8 * OUT_);
    vw[0][3] = ldg_u32(vbase + 9 * OUT_);

    __syncthreads();

    // ---- phase 2: softmax (exp2 domain); repack P as bf16-split in place ----
#pragma unroll 1
    for (int rr = 0; rr < 2; rr++) {
        int r = w * 2 + rr;
        float* srow = sS + r * SSTRW;
        float m = -3.402823466e38f;
#pragma unroll 8
        for (int j = 0; j < 32; j++) m = fmaxf(m, srow[j * 32 + lane]);
#pragma unroll
        for (int d = 16; d >= 1; d >>= 1) m = fmaxf(m, __shfl_xor_sync(0xffffffffu, m, d));
        float s = 0.f;
#pragma unroll 8
        for (int j = 0; j < 32; j++) {
            float e = ex2f_(srow[j * 32 + lane] - m);
            srow[j * 32 + lane] = e;
            s += e;
        }
#pragma unroll
        for (int d = 16; d >= 1; d >>= 1) s += __shfl_xor_sync(0xffffffffu, s, d);
        float inv = 1.0f / s;
        float* arow = attnOut + ((size_t)n * B_ + b0 + r) * L_;
        uint32_t* urow = (uint32_t*)srow;
#pragma unroll 8
        for (int j = 0; j < 32; j++) {
            float e = srow[j * 32 + lane];
            arow[j * 32 + lane] = e * inv;
            urow[j * 32 + lane] = pack_split(e);
        }
        if (lane == 0) sInv[r] = inv;
    }
    __syncthreads();

    // ---- phase 3: out = P @ V, S(smem)+V(gmem) double-buffer pipelined ----
    const uint32_t* sSu = (const uint32_t*)sS;
    const uint32_t* sp0 = sSu + gi * SSTRW + 2 * ti;
    float acc[2][4];
#pragma unroll
    for (int p = 0; p < 2; p++)
#pragma unroll
        for (int i = 0; i < 4; i++) acc[p][i] = 0.f;

    uint2 sw[2][4];
    sw[0][0] = *(const uint2*)(sp0);
    sw[0][1] = *(const uint2*)(sp0 + 8 * SSTRW);
    sw[0][2] = *(const uint2*)(sp0 + 8);
    sw[0][3] = *(const uint2*)(sp0 + 8 * SSTRW + 8);

#pragma unroll 4
    for (int ls = 0; ls < 64; ls++) {
        int cur = ls & 1, nxt = cur ^ 1;
        if (ls < 63) {   // prefetch next iteration (gmem V first, then smem S)
            const uint32_t* vp = vbase + (size_t)(ls + 1) * 16 * OUT_;
            vw[nxt][0] = ldg_u32(vp);
            vw[nxt][1] = ldg_u32(vp + OUT_);
            vw[nxt][2] = ldg_u32(vp + 8 * OUT_);
            vw[nxt][3] = ldg_u32(vp + 9 * OUT_);
            const uint32_t* sp = sp0 + (ls + 1) * 16;
            sw[nxt][0] = *(const uint2*)(sp);
            sw[nxt][1] = *(const uint2*)(sp + 8 * SSTRW);
            sw[nxt][2] = *(const uint2*)(sp + 8);
            sw[nxt][3] = *(const uint2*)(sp + 8 * SSTRW + 8);
        }
        uint32_t ah[4], al[4];
        unpack_pair(sw[cur][0], ah[0], al[0]);
        unpack_pair(sw[cur][1], ah[1], al[1]);
        unpack_pair(sw[cur][2], ah[2], al[2]);
        unpack_pair(sw[cur][3], ah[3], al[3]);
        uint32_t bh0 = prmt_(vw[cur][0], vw[cur][1], 0x7632);
        uint32_t bl0 = prmt_(vw[cur][0], vw[cur][1], 0x5410);
        uint32_t bh1 = prmt_(vw[cur][2], vw[cur][3], 0x7632);
        uint32_t bl1 = prmt_(vw[cur][2], vw[cur][3], 0x5410);
        mma_split16(acc[cur], ah, al, bh0, bh1, bl0, bl1);
    }

    // epilogue: scale by 1/rowsum, store result [B][N][64]
    {
        float i0 = sInv[gi], i1 = sInv[gi + 8];
        float c0 = acc[0][0] + acc[1][0];
        float c1 = acc[0][1] + acc[1][1];
        float c2 = acc[0][2] + acc[1][2];
        float c3 = acc[0][3] + acc[1][3];
        float* op0 = resOut + ((size_t)(b0 + gi) * N_ + n) * OUT_ + w * 8 + 2 * ti;
        float* op1 = resOut + ((size_t)(b0 + gi + 8) * N_ + n) * OUT_ + w * 8 + 2 * ti;
        *(float2*)op0 = make_float2(c0 * i0, c1 * i0);
        *(float2*)op1 = make_float2(c2 * i1, c3 * i1);
    }
}

// ----------------------------- launcher --------------------------------------
extern "C" void kernel_launch(void* const* d_in, const int* in_sizes, int n_in,
                              void* d_out, int out_size) {
    const float* queries = (const float*)d_in[0];
    const float* keys    = (const float*)d_in[1];
    const float* values  = (const float*)d_in[2];
    const float* Wq      = (const float*)d_in[3];
    const float* Wk      = (const float*)d_in[4];
    const float* Wv      = (const float*)d_in[5];

    float* resOut  = (float*)d_out;                      // [B, N, OUT]
    float* attnOut = resOut + (size_t)B_ * N_ * OUT_;    // [N, B, L]

    const int SMEM_ATTN = (ROWS_A * SSTRW + 16) * (int)sizeof(float);  // ~66 KB
    cudaFuncSetAttribute(attn_kernel, cudaFuncAttributeMaxDynamicSharedMemorySize, SMEM_ATTN);

    prep_kernel<<<B_ + 64, 256>>>(queries, Wq, Wk, Wv);
    proj_kernel<<<dim3((N_ * L_) / 128, 2), 256>>>(keys, values);
    attn_kernel<<<dim3(B_ / ROWS_A, N_), 256, SMEM_ATTN>>>(resOut, attnOut);
}